// round 2
// baseline (speedup 1.0000x reference)
#include <cuda_runtime.h>
#include <math_constants.h>

#define NI 16384          // inputs per batch row
#define ND 65536          // detectors
#define KK 32             // members per detector (== warp size)
#define BB 32             // batch
#define NCHUNK 16         // detector chunks
#define DET_PER_CTA (ND / NCHUNK)   // 4096
#define THREADS 256
#define SMEM_BYTES (NI * 4 + NI)    // 64KB x-row + 16KB byte map = 81920

__global__ void init_out_kernel(float4* __restrict__ out) {
    int i = blockIdx.x * blockDim.x + threadIdx.x;   // covers BB*NI/4 = 131072
    out[i] = make_float4(1.0f, 1.0f, 1.0f, 1.0f);
}

// Order-preserving float -> unsigned key: for x >= y (as floats, incl. -inf),
// key(x) >= key(y) as unsigned ints. Positive floats: flip sign bit.
// Negative floats: flip all bits. Equal floats -> equal keys.
__device__ __forceinline__ unsigned f32_order_key(float f) {
    unsigned u = __float_as_uint(f);
    return u ^ (((int)u >> 31) | 0x80000000u);
}

__global__ void __launch_bounds__(THREADS, 2) inhibit_kernel(
    const float* __restrict__ x,
    const int*   __restrict__ det,
    float*       __restrict__ out)
{
    extern __shared__ unsigned char smem[];
    float*         xs  = (float*)smem;          // 64KB: x row for this batch
    unsigned char* map = smem + NI * 4;         // 16KB: inhibited flags

    const int tid   = threadIdx.x;
    const int chunk = blockIdx.x;               // 0..15
    const int b     = blockIdx.y;               // 0..31

    // Load x row into SMEM (coalesced float4), zero the map.
    const float4* xrow = (const float4*)(x + (size_t)b * NI);
    float4* xs4 = (float4*)xs;
    #pragma unroll
    for (int i = tid; i < NI / 4; i += THREADS)
        xs4[i] = xrow[i];
    uint4* map16 = (uint4*)map;
    #pragma unroll
    for (int i = tid; i < NI / 16; i += THREADS)
        map16[i] = make_uint4(0u, 0u, 0u, 0u);
    __syncthreads();

    const int lane = tid & 31;
    const int warp = tid >> 5;
    const unsigned lt_mask = (1u << lane) - 1u;

    // Each warp owns detectors {chunk*4096 + warp + 8*i}, i in [0,512).
    // One detector row == 128B == exactly one coalesced warp load.
    const int* drow = det + ((size_t)(chunk * DET_PER_CTA + warp)) * KK + lane;

    #pragma unroll 4
    for (int i = 0; i < DET_PER_CTA / 8; i++) {
        int id = __ldg(drow + (size_t)i * 8 * KK);
        bool valid = (id >= 0);
        float v = -CUDART_INF_F;
        if (valid) v = xs[id];                       // predicated SMEM gather
        unsigned key = f32_order_key(v);
        unsigned mkey = __reduce_max_sync(0xffffffffu, key);
        bool eq = (key == mkey);
        unsigned bal = __ballot_sync(0xffffffffu, eq);
        // winner = lowest lane achieving max (matches jnp.argmax tie-break)
        bool winner = eq && ((bal & lt_mask) == 0u);
        if (valid && !winner) map[id] = 1;           // benign write race
    }
    __syncthreads();

    // Flush: write 0.0 for every inhibited input of this batch row.
    // Union across the 16 chunk-CTAs of a batch is formed by all of them
    // writing 0 (init kernel already wrote 1.0 everywhere).
    float* orow = out + (size_t)b * NI;
    for (int i = tid; i < NI; i += THREADS)
        if (map[i]) orow[i] = 0.0f;
}

extern "C" void kernel_launch(void* const* d_in, const int* in_sizes, int n_in,
                              void* d_out, int out_size) {
    const float* x   = (const float*)d_in[0];   // [32, 16384] f32
    const int*   det = (const int*)d_in[1];     // [65536, 32] i32
    float*       out = (float*)d_out;           // [32, 16384] f32

    (void)in_sizes; (void)n_in; (void)out_size;

    cudaFuncSetAttribute(inhibit_kernel,
                         cudaFuncAttributeMaxDynamicSharedMemorySize,
                         SMEM_BYTES);

    // Init output to 1.0 (spike unless inhibited).
    init_out_kernel<<<(BB * NI / 4) / THREADS, THREADS>>>((float4*)out);

    dim3 grid(NCHUNK, BB);
    inhibit_kernel<<<grid, THREADS, SMEM_BYTES>>>(x, det, out);
}

// round 3
// speedup vs baseline: 1.3631x; 1.3631x over previous
#include <cuda_runtime.h>
#include <math_constants.h>

#define NI 16384          // inputs per batch row
#define ND 65536          // detectors
#define KK 32             // members per detector (== warp size)
#define BB 32             // batch
#define NCHUNK 16         // detector chunks
#define DET_PER_CTA (ND / NCHUNK)   // 4096
#define THREADS 512
#define WARPS (THREADS / 32)        // 16
#define DET_PER_WARP (DET_PER_CTA / WARPS)  // 256
#define SMEM_BYTES (NI * 4 + NI)    // 64KB x-row + 16KB byte map = 81920

__global__ void init_out_kernel(float4* __restrict__ out) {
    int i = blockIdx.x * blockDim.x + threadIdx.x;   // covers BB*NI/4 = 131072
    out[i] = make_float4(1.0f, 1.0f, 1.0f, 1.0f);
}

// Order-preserving float -> unsigned key: x >= y (as floats, incl. -inf)
// iff key(x) >= key(y) as unsigned. Equal floats -> equal keys.
__device__ __forceinline__ unsigned f32_order_key(float f) {
    unsigned u = __float_as_uint(f);
    return u ^ (((int)u >> 31) | 0x80000000u);
}

__global__ void __launch_bounds__(THREADS, 2) inhibit_kernel(
    const float* __restrict__ x,
    const int*   __restrict__ det,
    float*       __restrict__ out)
{
    extern __shared__ unsigned char smem[];
    float*         xs  = (float*)smem;          // 64KB: x row for this batch
    unsigned char* map = smem + NI * 4;         // 16KB: inhibited flags

    const int tid   = threadIdx.x;
    const int chunk = blockIdx.x;               // 0..15
    const int b     = blockIdx.y;               // 0..31

    // Load x row into SMEM (coalesced float4), zero the map.
    const float4* xrow = (const float4*)(x + (size_t)b * NI);
    float4* xs4 = (float4*)xs;
    #pragma unroll
    for (int i = tid; i < NI / 4; i += THREADS)
        xs4[i] = xrow[i];
    uint4* map16 = (uint4*)map;
    #pragma unroll
    for (int i = tid; i < NI / 16; i += THREADS)
        map16[i] = make_uint4(0u, 0u, 0u, 0u);
    __syncthreads();

    const int lane = tid & 31;
    const int warp = tid >> 5;
    const unsigned lt_mask = (1u << lane) - 1u;

    // Warp w owns detectors {chunk*4096 + w*256 ... +255}; one detector row
    // == 128B == exactly one coalesced warp load.
    const int* drow = det
        + ((size_t)(chunk * DET_PER_CTA + warp * DET_PER_WARP)) * KK + lane;

    #pragma unroll 4
    for (int i = 0; i < DET_PER_WARP; i++) {
        int id = __ldg(drow + (size_t)i * KK);
        bool valid = (id >= 0);
        float v = -CUDART_INF_F;
        if (valid) v = xs[id];                       // predicated SMEM gather
        unsigned key = f32_order_key(v);
        unsigned mkey = __reduce_max_sync(0xffffffffu, key);
        bool eq = (key == mkey);
        unsigned bal = __ballot_sync(0xffffffffu, eq);
        // winner = lowest lane achieving max (matches jnp.argmax tie-break)
        bool winner = eq && ((bal & lt_mask) == 0u);
        if (valid && !winner) map[id] = 1;           // benign write race
    }
    __syncthreads();

    // Flush: write 0.0 for every inhibited input of this batch row.
    // Union across the 16 chunk-CTAs of a batch is formed by all of them
    // writing 0 (init kernel already wrote 1.0 everywhere).
    float* orow = out + (size_t)b * NI;
    for (int i = tid; i < NI; i += THREADS)
        if (map[i]) orow[i] = 0.0f;
}

extern "C" void kernel_launch(void* const* d_in, const int* in_sizes, int n_in,
                              void* d_out, int out_size) {
    const float* x   = (const float*)d_in[0];   // [32, 16384] f32
    const int*   det = (const int*)d_in[1];     // [65536, 32] i32
    float*       out = (float*)d_out;           // [32, 16384] f32

    (void)in_sizes; (void)n_in; (void)out_size;

    cudaFuncSetAttribute(inhibit_kernel,
                         cudaFuncAttributeMaxDynamicSharedMemorySize,
                         SMEM_BYTES);

    // Init output to 1.0 (spike unless inhibited).
    init_out_kernel<<<(BB * NI / 4) / THREADS, THREADS>>>((float4*)out);

    dim3 grid(NCHUNK, BB);
    inhibit_kernel<<<grid, THREADS, SMEM_BYTES>>>(x, det, out);
}

// round 4
// speedup vs baseline: 1.3862x; 1.0170x over previous
#include <cuda_runtime.h>
#include <math_constants.h>

#define NI 16384          // inputs per batch row
#define ND 65536          // detectors
#define KK 32             // members per detector (== warp size)
#define BB 32             // batch
#define NCHUNK 16         // detector chunks
#define DET_PER_CTA (ND / NCHUNK)   // 4096
#define THREADS 1024
#define WARPS (THREADS / 32)        // 32
#define DET_PER_WARP (DET_PER_CTA / WARPS)  // 128
#define SMEM_BYTES (NI * 4 + NI)    // 64KB x-row + 16KB byte map = 81920

__global__ void init_out_kernel(float4* __restrict__ out) {
    int i = blockIdx.x * blockDim.x + threadIdx.x;   // covers BB*NI/4
    out[i] = make_float4(1.0f, 1.0f, 1.0f, 1.0f);
}

// Order-preserving float -> unsigned key: x >= y (as floats, incl. -inf)
// iff key(x) >= key(y) as unsigned. Equal floats -> equal keys.
__device__ __forceinline__ unsigned f32_order_key(float f) {
    unsigned u = __float_as_uint(f);
    return u ^ (((int)u >> 31) | 0x80000000u);
}

__global__ void __launch_bounds__(THREADS, 2) inhibit_kernel(
    const float* __restrict__ x,
    const int*   __restrict__ det,
    float*       __restrict__ out)
{
    extern __shared__ unsigned char smem[];
    float*         xs  = (float*)smem;          // 64KB: x row for this batch
    unsigned char* map = smem + NI * 4;         // 16KB: inhibited flags

    const int tid   = threadIdx.x;
    const int chunk = blockIdx.x;               // 0..15
    const int b     = blockIdx.y;               // 0..31

    // Load x row into SMEM (coalesced float4), zero the map.
    const float4* xrow = (const float4*)(x + (size_t)b * NI);
    float4* xs4 = (float4*)xs;
    #pragma unroll
    for (int i = tid; i < NI / 4; i += THREADS)
        xs4[i] = xrow[i];
    uint4* map16 = (uint4*)map;
    #pragma unroll
    for (int i = tid; i < NI / 16; i += THREADS)
        map16[i] = make_uint4(0u, 0u, 0u, 0u);
    __syncthreads();

    const int lane = tid & 31;
    const int warp = tid >> 5;
    const unsigned lt_mask = (1u << lane) - 1u;

    // Warp w owns DET_PER_WARP consecutive detectors; one detector row
    // == 128B == exactly one coalesced warp load. 32-bit offsets (det is
    // 8MB total) keep register pressure down for the 32-reg budget.
    const int* dbase = det
        + ((size_t)(chunk * DET_PER_CTA + warp * DET_PER_WARP)) * KK + lane;

    #pragma unroll 4
    for (int i = 0; i < DET_PER_WARP; i++) {
        int id = __ldg(dbase + i * KK);
        bool valid = (id >= 0);
        float v = -CUDART_INF_F;
        if (valid) v = xs[id];                       // predicated SMEM gather
        unsigned key = f32_order_key(v);
        unsigned mkey = __reduce_max_sync(0xffffffffu, key);
        bool eq = (key == mkey);
        unsigned bal = __ballot_sync(0xffffffffu, eq);
        // winner = lowest lane achieving max (matches jnp.argmax tie-break)
        bool winner = eq && ((bal & lt_mask) == 0u);
        if (valid && !winner) map[id] = 1;           // benign write race
    }
    __syncthreads();

    // Flush: write 0.0 for every inhibited input of this batch row.
    // Union across the 16 chunk-CTAs of a batch is formed by all of them
    // writing 0 (init kernel already wrote 1.0 everywhere).
    float* orow = out + (size_t)b * NI;
    for (int i = tid; i < NI; i += THREADS)
        if (map[i]) orow[i] = 0.0f;
}

extern "C" void kernel_launch(void* const* d_in, const int* in_sizes, int n_in,
                              void* d_out, int out_size) {
    const float* x   = (const float*)d_in[0];   // [32, 16384] f32
    const int*   det = (const int*)d_in[1];     // [65536, 32] i32
    float*       out = (float*)d_out;           // [32, 16384] f32

    (void)in_sizes; (void)n_in; (void)out_size;

    cudaFuncSetAttribute(inhibit_kernel,
                         cudaFuncAttributeMaxDynamicSharedMemorySize,
                         SMEM_BYTES);

    // Init output to 1.0 (spike unless inhibited).
    init_out_kernel<<<(BB * NI / 4) / 256, 256>>>((float4*)out);

    dim3 grid(NCHUNK, BB);
    inhibit_kernel<<<grid, THREADS, SMEM_BYTES>>>(x, det, out);
}